// round 4
// baseline (speedup 1.0000x reference)
#include <cuda_runtime.h>
#include <cuda_bf16.h>
#include <cuda_fp8.h>
#include <cstdint>

#define MDIM  128
#define FEAT  8256          // MDIM*(MDIM+1)/2
#define HID   1651
#define NP    1792          // HID padded to 14*128
#define KP    8320          // FEAT padded to 65*128
#define BATCH 4096
#define KST   65            // KP / 128

#define SCALE_W   8192.0f
#define INV_S     (1.0f/8192.0f)

#define STAGE_BYTES 32768   // A: 128x128B + B: 128x128B
#define B_OFF       16384
#define SMEM_TOTAL  (2 * STAGE_BYTES)

// ---------------- device scratch ----------------
__device__ uint8_t g_x8 [(size_t)BATCH * KP];   // 34.1 MB fp8
__device__ uint8_t g_w18[(size_t)NP    * KP];   // 14.9 MB fp8
__device__ float g_b1[NP];
__device__ float g_w2[NP];
__device__ float g_logits[BATCH];

// ---------------- helpers ----------------
__device__ __forceinline__ uint32_t smem_u32(const void* p) {
    uint32_t a;
    asm("{ .reg .u64 t; cvta.to.shared.u64 t, %1; cvt.u32.u64 %0, t; }" : "=r"(a) : "l"(p));
    return a;
}
#define SWZ128(off) ((off) ^ (((off) >> 3) & 0x70))

__device__ __forceinline__ void ldsm_x4(uint32_t& r0, uint32_t& r1, uint32_t& r2, uint32_t& r3,
                                        uint32_t addr) {
    asm volatile("ldmatrix.sync.aligned.m8n8.x4.shared.b16 {%0,%1,%2,%3}, [%4];"
                 : "=r"(r0), "=r"(r1), "=r"(r2), "=r"(r3) : "r"(addr));
}
__device__ __forceinline__ void mma_e4m3(float* c, const uint32_t* a, const uint32_t* b) {
    asm volatile(
        "mma.sync.aligned.m16n8k32.row.col.f32.e4m3.e4m3.f32 "
        "{%0,%1,%2,%3}, {%4,%5,%6,%7}, {%8,%9}, {%0,%1,%2,%3};"
        : "+f"(c[0]), "+f"(c[1]), "+f"(c[2]), "+f"(c[3])
        : "r"(a[0]), "r"(a[1]), "r"(a[2]), "r"(a[3]), "r"(b[0]), "r"(b[1]));
}

// ---------------- prep kernels ----------------
__global__ void prep_small(const float* __restrict__ b1, const float* __restrict__ w2) {
    int i = blockIdx.x * blockDim.x + threadIdx.x;
    if (i < NP) {
        g_b1[i] = (i < HID) ? b1[i] : 0.0f;
        g_w2[i] = (i < HID) ? w2[i] : 0.0f;
    }
    if (i < BATCH) g_logits[i] = 0.0f;
}

// W1 fp32 -> fp8 (scaled): float4 loads, uint32 stores
__global__ void prep_w18(const float* __restrict__ W1) {
    int n  = blockIdx.y;
    int k4 = blockIdx.x * blockDim.x + threadIdx.x;
    if (k4 >= KP / 4) return;
    uint32_t out = 0;
    if (n < HID) {
        int k = k4 * 4;
        if (k + 3 < FEAT) {
            float4 v = *(const float4*)&W1[(size_t)n * FEAT + k];
            out  = (uint32_t)__nv_cvt_float_to_fp8(v.x * SCALE_W, __NV_SATFINITE, __NV_E4M3);
            out |= (uint32_t)__nv_cvt_float_to_fp8(v.y * SCALE_W, __NV_SATFINITE, __NV_E4M3) << 8;
            out |= (uint32_t)__nv_cvt_float_to_fp8(v.z * SCALE_W, __NV_SATFINITE, __NV_E4M3) << 16;
            out |= (uint32_t)__nv_cvt_float_to_fp8(v.w * SCALE_W, __NV_SATFINITE, __NV_E4M3) << 24;
        } else {
#pragma unroll
            for (int j = 0; j < 4; j++) {
                float v = (k + j < FEAT) ? W1[(size_t)n * FEAT + k + j] * SCALE_W : 0.0f;
                out |= (uint32_t)__nv_cvt_float_to_fp8(v, __NV_SATFINITE, __NV_E4M3) << (8 * j);
            }
        }
    }
    ((uint32_t*)g_w18)[(size_t)n * (KP / 4) + k4] = out;
}

// triu extraction + fp8 convert, float4 loads, lower-triangle groups skipped
__global__ __launch_bounds__(256) void triu8(const float* __restrict__ sim) {
    int b   = blockIdx.x;
    int tid = threadIdx.x;
    const float* base = sim + (size_t)b * MDIM * MDIM;
    uint8_t* out = g_x8 + (size_t)b * KP;
#pragma unroll
    for (int it = 0; it < 16; ++it) {
        int idx = tid + it * 256;       // 0..4095: (row, group-of-4)
        int i = idx >> 5;
        int g = idx & 31;
        int j0 = g * 4;
        if (j0 + 3 >= i) {
            float4 v = *(const float4*)&base[i * MDIM + j0];
            int rowoff = i * MDIM - (i * (i - 1)) / 2 - i;   // out index = rowoff + j
            float vv[4] = {v.x, v.y, v.z, v.w};
#pragma unroll
            for (int l = 0; l < 4; l++) {
                int j = j0 + l;
                if (j >= i)
                    out[rowoff + j] = __nv_cvt_float_to_fp8(vv[l], __NV_SATFINITE, __NV_E4M3);
            }
        }
    }
    if (tid < KP - FEAT) out[FEAT + tid] = 0;
}

// ---------------- fp8 GEMM: CTA 128x128, 4 warps (64x64 each), 2-stage, 3 CTA/SM ----------------
__global__ __launch_bounds__(128, 3) void gemm_fp8() {
    extern __shared__ __align__(1024) uint8_t smem[];
    const uint32_t sbase = smem_u32(smem);
    const int tid = threadIdx.x;
    const int wid = tid >> 5;
    const int lid = tid & 31;
    const int wm  = wid & 1;            // 2 M halves of 64
    const int wn  = wid >> 1;           // 2 N halves of 64
    const int m0  = blockIdx.y * 128;
    const int n0  = blockIdx.x * 128;

    // ldmatrix per-thread geometry (same mapping validated in round 3)
    const int aRow0 = wm * 64 + ((lid >> 3) & 1) * 8 + (lid & 7);   // + mi*16
    const int aCol  = (lid >> 4) * 16;
    const int bRow0 = wn * 64 + (lid >> 4) * 8 + (lid & 7);         // + p*16
    const int bCol  = ((lid >> 3) & 1) * 16;

    float acc[4][8][4];
#pragma unroll
    for (int mi = 0; mi < 4; mi++)
#pragma unroll
        for (int ni = 0; ni < 8; ni++)
#pragma unroll
            for (int c = 0; c < 4; c++) acc[mi][ni][c] = 0.0f;

    auto load_stage = [&](int buf, int kByte) {
        uint32_t st = sbase + buf * STAGE_BYTES;
#pragma unroll
        for (int it = 0; it < 16; ++it) {
            int idx = tid + it * 128;           // 0..2047 16B chunks
            int isB = idx >> 10;
            int r   = (idx >> 3) & 127;
            int c   = idx & 7;
            const uint8_t* src = isB
                ? &g_w18[(size_t)(n0 + r) * KP + kByte + c * 16]
                : &g_x8 [(size_t)(m0 + r) * KP + kByte + c * 16];
            uint32_t dst = st + (isB ? B_OFF : 0) + SWZ128((uint32_t)(r * 128 + c * 16));
            asm volatile("cp.async.cg.shared.global [%0], [%1], 16;"
                         :: "r"(dst), "l"(src) : "memory");
        }
        asm volatile("cp.async.commit_group;" ::: "memory");
    };

    load_stage(0, 0);
    load_stage(1, 128);

    for (int s = 0; s < KST; ++s) {
        asm volatile("cp.async.wait_group 1;" ::: "memory");
        __syncthreads();

        uint32_t Ab = sbase + (s & 1) * STAGE_BYTES;
        uint32_t Bb = Ab + B_OFF;

#pragma unroll
        for (int ks = 0; ks < 4; ++ks) {
            // B fragments: 8 n8-frags via 4 ldsm.x4
            uint32_t b[8][2];
#pragma unroll
            for (int p = 0; p < 4; p++) {
                uint32_t off = (uint32_t)((bRow0 + p * 16) * 128 + ks * 32 + bCol);
                uint32_t r0, r1, r2, r3;
                ldsm_x4(r0, r1, r2, r3, Bb + SWZ128(off));
                b[2 * p][0] = r0; b[2 * p][1] = r1;
                b[2 * p + 1][0] = r2; b[2 * p + 1][1] = r3;
            }
            // A fragments streamed 2-deep: 4 m16-frags, 8 MMAs each
            uint32_t a[2][4];
            {
                uint32_t off = (uint32_t)(aRow0 * 128 + ks * 32 + aCol);
                ldsm_x4(a[0][0], a[0][1], a[0][2], a[0][3], Ab + SWZ128(off));
            }
#pragma unroll
            for (int mi = 0; mi < 4; mi++) {
                if (mi < 3) {
                    uint32_t off = (uint32_t)((aRow0 + (mi + 1) * 16) * 128 + ks * 32 + aCol);
                    ldsm_x4(a[(mi + 1) & 1][0], a[(mi + 1) & 1][1],
                            a[(mi + 1) & 1][2], a[(mi + 1) & 1][3], Ab + SWZ128(off));
                }
#pragma unroll
                for (int ni = 0; ni < 8; ni++)
                    mma_e4m3(acc[mi][ni], a[mi & 1], b[ni]);
            }
        }
        __syncthreads();   // all reads of this buffer done

        if (s + 2 < KST) load_stage(s & 1, (s + 2) * 128);
        else             asm volatile("cp.async.commit_group;" ::: "memory");
    }

    // -------- fused epilogue: logits[m] += sum_n relu(acc*INV_S + b1) * w2 --------
    const int qrow = lid >> 2;
    const int qcol = lid & 3;
#pragma unroll
    for (int mi = 0; mi < 4; mi++) {
        float r0 = 0.f, r1 = 0.f;
#pragma unroll
        for (int ni = 0; ni < 8; ni++) {
            int n = n0 + wn * 64 + ni * 8 + qcol * 2;
            float b1a = g_b1[n],     w2a = g_w2[n];
            float b1b = g_b1[n + 1], w2b = g_w2[n + 1];
            r0 += fmaxf(fmaf(acc[mi][ni][0], INV_S, b1a), 0.f) * w2a
                + fmaxf(fmaf(acc[mi][ni][1], INV_S, b1b), 0.f) * w2b;
            r1 += fmaxf(fmaf(acc[mi][ni][2], INV_S, b1a), 0.f) * w2a
                + fmaxf(fmaf(acc[mi][ni][3], INV_S, b1b), 0.f) * w2b;
        }
        r0 += __shfl_xor_sync(0xffffffffu, r0, 1);
        r0 += __shfl_xor_sync(0xffffffffu, r0, 2);
        r1 += __shfl_xor_sync(0xffffffffu, r1, 1);
        r1 += __shfl_xor_sync(0xffffffffu, r1, 2);
        if (qcol == 0) {
            int row = m0 + wm * 64 + mi * 16 + qrow;
            atomicAdd(&g_logits[row],     r0);
            atomicAdd(&g_logits[row + 8], r1);
        }
    }
}

// ---------------- finalize ----------------
__global__ void finalize(const float* __restrict__ b2, float* __restrict__ out) {
    int i = blockIdx.x * blockDim.x + threadIdx.x;
    if (i < BATCH) {
        float z = g_logits[i] + b2[0];
        out[i] = 1.0f / (1.0f + expf(-z));
    }
}

// ---------------- launch ----------------
extern "C" void kernel_launch(void* const* d_in, const int* in_sizes, int n_in,
                              void* d_out, int out_size) {
    const float* sim = (const float*)d_in[0];
    const float* W1  = (const float*)d_in[1];
    const float* b1  = (const float*)d_in[2];
    const float* W2  = (const float*)d_in[3];
    const float* b2  = (const float*)d_in[4];
    float* out = (float*)d_out;

    cudaFuncSetAttribute(gemm_fp8, cudaFuncAttributeMaxDynamicSharedMemorySize, SMEM_TOTAL);

    prep_small<<<(BATCH + 255) / 256, 256>>>(b1, W2);
    prep_w18<<<dim3((KP / 4 + 255) / 256, NP), 256>>>(W1);
    triu8<<<BATCH, 256>>>(sim);
    gemm_fp8<<<dim3(NP / 128, BATCH / 128), 128, SMEM_TOTAL>>>();
    finalize<<<(BATCH + 255) / 256, 256>>>(b2, out);
}

// round 5
// speedup vs baseline: 1.1168x; 1.1168x over previous
#include <cuda_runtime.h>
#include <cuda_bf16.h>
#include <cuda_fp8.h>
#include <cstdint>

#define MDIM  128
#define FEAT  8256          // MDIM*(MDIM+1)/2
#define HID   1651
#define NP    1664          // HID padded to 13*128
#define KP    8320          // FEAT padded to 65*128
#define BATCH 4096
#define KST   65            // KP / 128

#define SCALE_W   8192.0f
#define INV_S     (1.0f/8192.0f)

#define A_BYTES     32768   // 256 rows x 128B
#define B_BYTES     16384   // 128 rows x 128B
#define STAGE_BYTES (A_BYTES + B_BYTES)
#define NSTAGE      3
#define SMEM_TOTAL  (NSTAGE * STAGE_BYTES)   // 144 KB

// ---------------- device scratch ----------------
__device__ uint8_t g_x8 [(size_t)BATCH * KP];   // 34.1 MB fp8
__device__ uint8_t g_w18[(size_t)NP    * KP];   // 13.8 MB fp8
__device__ float g_b1[NP];
__device__ float g_w2[NP];
__device__ float g_logits[BATCH];

// ---------------- helpers ----------------
__device__ __forceinline__ uint32_t smem_u32(const void* p) {
    uint32_t a;
    asm("{ .reg .u64 t; cvta.to.shared.u64 t, %1; cvt.u32.u64 %0, t; }" : "=r"(a) : "l"(p));
    return a;
}
#define SWZ128(off) ((off) ^ (((off) >> 3) & 0x70))

__device__ __forceinline__ void ldsm_x4(uint32_t& r0, uint32_t& r1, uint32_t& r2, uint32_t& r3,
                                        uint32_t addr) {
    asm volatile("ldmatrix.sync.aligned.m8n8.x4.shared.b16 {%0,%1,%2,%3}, [%4];"
                 : "=r"(r0), "=r"(r1), "=r"(r2), "=r"(r3) : "r"(addr));
}
__device__ __forceinline__ void mma_e4m3(float* c, const uint32_t* a, const uint32_t* b) {
    asm volatile(
        "mma.sync.aligned.m16n8k32.row.col.f32.e4m3.e4m3.f32 "
        "{%0,%1,%2,%3}, {%4,%5,%6,%7}, {%8,%9}, {%0,%1,%2,%3};"
        : "+f"(c[0]), "+f"(c[1]), "+f"(c[2]), "+f"(c[3])
        : "r"(a[0]), "r"(a[1]), "r"(a[2]), "r"(a[3]), "r"(b[0]), "r"(b[1]));
}

// ---------------- prep kernels ----------------
__global__ void prep_small(const float* __restrict__ b1, const float* __restrict__ w2) {
    int i = blockIdx.x * blockDim.x + threadIdx.x;
    if (i < NP) {
        g_b1[i] = (i < HID) ? b1[i] : 0.0f;
        g_w2[i] = (i < HID) ? w2[i] : 0.0f;
    }
    if (i < BATCH) g_logits[i] = 0.0f;
}

// W1 fp32 -> fp8 (scaled): float4 loads, uint32 stores
__global__ void prep_w18(const float* __restrict__ W1) {
    int n  = blockIdx.y;
    int k4 = blockIdx.x * blockDim.x + threadIdx.x;
    if (k4 >= KP / 4) return;
    uint32_t out = 0;
    if (n < HID) {
        int k = k4 * 4;
        if (k + 3 < FEAT) {
            float4 v = *(const float4*)&W1[(size_t)n * FEAT + k];
            out  = (uint32_t)__nv_cvt_float_to_fp8(v.x * SCALE_W, __NV_SATFINITE, __NV_E4M3);
            out |= (uint32_t)__nv_cvt_float_to_fp8(v.y * SCALE_W, __NV_SATFINITE, __NV_E4M3) << 8;
            out |= (uint32_t)__nv_cvt_float_to_fp8(v.z * SCALE_W, __NV_SATFINITE, __NV_E4M3) << 16;
            out |= (uint32_t)__nv_cvt_float_to_fp8(v.w * SCALE_W, __NV_SATFINITE, __NV_E4M3) << 24;
        } else {
#pragma unroll
            for (int j = 0; j < 4; j++) {
                float v = (k + j < FEAT) ? W1[(size_t)n * FEAT + k + j] * SCALE_W : 0.0f;
                out |= (uint32_t)__nv_cvt_float_to_fp8(v, __NV_SATFINITE, __NV_E4M3) << (8 * j);
            }
        }
    }
    ((uint32_t*)g_w18)[(size_t)n * (KP / 4) + k4] = out;
}

// triu extraction + fp8 convert, float4 loads, lower-triangle groups skipped
__global__ __launch_bounds__(256) void triu8(const float* __restrict__ sim) {
    int b   = blockIdx.x;
    int tid = threadIdx.x;
    const float* base = sim + (size_t)b * MDIM * MDIM;
    uint8_t* out = g_x8 + (size_t)b * KP;
#pragma unroll
    for (int it = 0; it < 16; ++it) {
        int idx = tid + it * 256;       // 0..4095: (row, group-of-4)
        int i = idx >> 5;
        int g = idx & 31;
        int j0 = g * 4;
        if (j0 + 3 >= i) {
            float4 v = *(const float4*)&base[i * MDIM + j0];
            int rowoff = i * MDIM - (i * (i - 1)) / 2 - i;   // out index = rowoff + j
            float vv[4] = {v.x, v.y, v.z, v.w};
#pragma unroll
            for (int l = 0; l < 4; l++) {
                int j = j0 + l;
                if (j >= i)
                    out[rowoff + j] = __nv_cvt_float_to_fp8(vv[l], __NV_SATFINITE, __NV_E4M3);
            }
        }
    }
    if (tid < KP - FEAT) out[FEAT + tid] = 0;
}

// ---------------- fp8 GEMM: CTA 256x128, 8 warps (64x64 each), 3-stage, 1 CTA/SM ----------------
__global__ __launch_bounds__(256, 1) void gemm_fp8() {
    extern __shared__ __align__(1024) uint8_t smem[];
    const uint32_t sbase = smem_u32(smem);
    const int tid = threadIdx.x;
    const int wid = tid >> 5;
    const int lid = tid & 31;
    const int wm  = wid >> 1;           // 4 M quarters of 64
    const int wn  = wid & 1;            // 2 N halves of 64
    const int m0  = blockIdx.y * 256;
    const int n0  = blockIdx.x * 128;

    // ldmatrix per-thread geometry (mapping validated rounds 3-4)
    const int aRow0 = wm * 64 + ((lid >> 3) & 1) * 8 + (lid & 7);   // + mi*16
    const int aCol  = (lid >> 4) * 16;
    const int bRow0 = wn * 64 + (lid >> 4) * 8 + (lid & 7);         // + p*16
    const int bCol  = ((lid >> 3) & 1) * 16;

    float acc[4][8][4];
#pragma unroll
    for (int mi = 0; mi < 4; mi++)
#pragma unroll
        for (int ni = 0; ni < 8; ni++)
#pragma unroll
            for (int c = 0; c < 4; c++) acc[mi][ni][c] = 0.0f;

    auto load_stage = [&](int buf, int kByte) {
        uint32_t st = sbase + buf * STAGE_BYTES;
        // A: 2048 chunks (256 rows x 8), B: 1024 chunks (128 rows x 8); 12/thread
#pragma unroll
        for (int it = 0; it < 12; ++it) {
            int idx = tid + it * 256;           // 0..3071
            bool isB = idx >= 2048;
            int rel  = isB ? (idx - 2048) : idx;
            int r    = rel >> 3;
            int c    = rel & 7;
            const uint8_t* src = isB
                ? &g_w18[(size_t)(n0 + r) * KP + kByte + c * 16]
                : &g_x8 [(size_t)(m0 + r) * KP + kByte + c * 16];
            uint32_t dst = st + (isB ? A_BYTES : 0) + SWZ128((uint32_t)(r * 128 + c * 16));
            asm volatile("cp.async.cg.shared.global [%0], [%1], 16;"
                         :: "r"(dst), "l"(src) : "memory");
        }
        asm volatile("cp.async.commit_group;" ::: "memory");
    };

    load_stage(0, 0);
    load_stage(1, 128);

    for (int s = 0; s < KST; ++s) {
        asm volatile("cp.async.wait_group 1;" ::: "memory");
        __syncthreads();

        if (s + 2 < KST) load_stage((s + 2) % NSTAGE, (s + 2) * 128);
        else             asm volatile("cp.async.commit_group;" ::: "memory");

        uint32_t Ab = sbase + (s % NSTAGE) * STAGE_BYTES;
        uint32_t Bb = Ab + A_BYTES;

#pragma unroll
        for (int ks = 0; ks < 4; ++ks) {
            // B fragments: 8 n8-frags via 4 ldsm.x4
            uint32_t b[8][2];
#pragma unroll
            for (int p = 0; p < 4; p++) {
                uint32_t off = (uint32_t)((bRow0 + p * 16) * 128 + ks * 32 + bCol);
                uint32_t r0, r1, r2, r3;
                ldsm_x4(r0, r1, r2, r3, Bb + SWZ128(off));
                b[2 * p][0] = r0; b[2 * p][1] = r1;
                b[2 * p + 1][0] = r2; b[2 * p + 1][1] = r3;
            }
            // A fragments streamed 2-deep: 4 m16-frags, 8 MMAs each
            uint32_t a[2][4];
            {
                uint32_t off = (uint32_t)(aRow0 * 128 + ks * 32 + aCol);
                ldsm_x4(a[0][0], a[0][1], a[0][2], a[0][3], Ab + SWZ128(off));
            }
#pragma unroll
            for (int mi = 0; mi < 4; mi++) {
                if (mi < 3) {
                    uint32_t off = (uint32_t)((aRow0 + (mi + 1) * 16) * 128 + ks * 32 + aCol);
                    ldsm_x4(a[(mi + 1) & 1][0], a[(mi + 1) & 1][1],
                            a[(mi + 1) & 1][2], a[(mi + 1) & 1][3], Ab + SWZ128(off));
                }
#pragma unroll
                for (int ni = 0; ni < 8; ni++)
                    mma_e4m3(acc[mi][ni], a[mi & 1], b[ni]);
            }
        }
    }

    // -------- fused epilogue: logits[m] += sum_n relu(acc*INV_S + b1) * w2 --------
    const int qrow = lid >> 2;
    const int qcol = lid & 3;
#pragma unroll
    for (int mi = 0; mi < 4; mi++) {
        float r0 = 0.f, r1 = 0.f;
#pragma unroll
        for (int ni = 0; ni < 8; ni++) {
            int n = n0 + wn * 64 + ni * 8 + qcol * 2;
            float b1a = g_b1[n],     w2a = g_w2[n];
            float b1b = g_b1[n + 1], w2b = g_w2[n + 1];
            r0 += fmaxf(fmaf(acc[mi][ni][0], INV_S, b1a), 0.f) * w2a
                + fmaxf(fmaf(acc[mi][ni][1], INV_S, b1b), 0.f) * w2b;
            r1 += fmaxf(fmaf(acc[mi][ni][2], INV_S, b1a), 0.f) * w2a
                + fmaxf(fmaf(acc[mi][ni][3], INV_S, b1b), 0.f) * w2b;
        }
        r0 += __shfl_xor_sync(0xffffffffu, r0, 1);
        r0 += __shfl_xor_sync(0xffffffffu, r0, 2);
        r1 += __shfl_xor_sync(0xffffffffu, r1, 1);
        r1 += __shfl_xor_sync(0xffffffffu, r1, 2);
        if (qcol == 0) {
            int row = m0 + wm * 64 + mi * 16 + qrow;
            atomicAdd(&g_logits[row],     r0);
            atomicAdd(&g_logits[row + 8], r1);
        }
    }
}

// ---------------- finalize ----------------
__global__ void finalize(const float* __restrict__ b2, float* __restrict__ out) {
    int i = blockIdx.x * blockDim.x + threadIdx.x;
    if (i < BATCH) {
        float z = g_logits[i] + b2[0];
        out[i] = 1.0f / (1.0f + expf(-z));
    }
}

// ---------------- launch ----------------
extern "C" void kernel_launch(void* const* d_in, const int* in_sizes, int n_in,
                              void* d_out, int out_size) {
    const float* sim = (const float*)d_in[0];
    const float* W1  = (const float*)d_in[1];
    const float* b1  = (const float*)d_in[2];
    const float* W2  = (const float*)d_in[3];
    const float* b2  = (const float*)d_in[4];
    float* out = (float*)d_out;

    cudaFuncSetAttribute(gemm_fp8, cudaFuncAttributeMaxDynamicSharedMemorySize, SMEM_TOTAL);

    prep_small<<<(BATCH + 255) / 256, 256>>>(b1, W2);
    prep_w18<<<dim3((KP / 4 + 255) / 256, NP), 256>>>(W1);
    triu8<<<BATCH, 256>>>(sim);
    gemm_fp8<<<dim3(NP / 128, BATCH / 256), 256, SMEM_TOTAL>>>();
    finalize<<<(BATCH + 255) / 256, 256>>>(b2, out);
}